// round 15
// baseline (speedup 1.0000x reference)
#include <cuda_runtime.h>
#include <cuda_fp16.h>
#include <mma.h>
#include <cstdint>

using namespace nvcuda;

#define NU 50000
#define NI 25000
#define DIMV 128
#define EHMAX 600000
#define ERMAX 1000000
#define CHUNK 1024
#define NCHU 49
#define OSTR 50016

#define UF ((size_t)NU * DIMV)
#define IFl ((size_t)NI * DIMV)

// ------------------- fp16 scratch (everything) -------------------
#define H_GATE ((size_t)0)          // 4 channels
#define H_CURA (4 * UF)             // 3 channels, layer-1 H outputs (raw)
#define H_MIX  (7 * UF)
#define H_S1   (8 * UF)
#define H_N1   (9 * UF)             // 3 channels, l2n(layer-1 H outputs)
#define H_N2   (12 * UF)            // 3 channels, l2n(layer-2 H outputs)
#define H_S1N  (15 * UF)            // l2n(layer-1 R output)
#define H_S2N  (16 * UF)            // l2n(layer-2 R output)
#define H_I1   (17 * UF)
#define H_I1N  (17 * UF + IFl)      // l2n(layer-1 RT output)
#define H_I2N  (17 * UF + 2 * IFl)  // l2n(layer-2 RT output)
#define H_IEMB (17 * UF + 3 * IFl)
#define TOTALH (17 * UF + 4 * IFl)
__device__ __align__(16) __half g_hbuf[TOTALH];

__device__ float g_attvec[DIMV];

// ------------------- CSR scratch -------------------
#define CNT_TOT (4 * NU + NI)
#define OFFS_TOT (4 * OSTR + NI + 16)
#define PE_TOT (3 * EHMAX + 2 * ERMAX)
__device__ __align__(16) int g_cnt[CNT_TOT];
__device__ __align__(16) int g_cur[CNT_TOT];
__device__ __align__(16) int g_offs[OFFS_TOT];
__device__ __align__(16) int2 g_pair[PE_TOT];
__device__ int g_aux[5 * 64];

// ------------------- attention vector: v = M @ a -------------------
__global__ void attvec_kernel(const float* __restrict__ att, const float* __restrict__ mat) {
    int j = threadIdx.x;
    float s = 0.f;
#pragma unroll 8
    for (int d = 0; d < DIMV; d++) s += mat[j * DIMV + d] * att[d];
    g_attvec[j] = s;
}

// ------------------- f32 -> f16 conversion -------------------
__global__ void __launch_bounds__(256) f2h_kernel(const float* __restrict__ src,
                                                  __half* __restrict__ dst, int n4) {
    int i = blockIdx.x * 256 + threadIdx.x;
    if (i < n4) {
        float4 v = __ldg((const float4*)src + i);
        union { __half2 h[2]; uint2 u; } cv;
        cv.h[0] = __floats2half2_rn(v.x, v.y);
        cv.h[1] = __floats2half2_rn(v.z, v.w);
        *(uint2*)(dst + (size_t)i * 4) = cv.u;
    }
}

// ------------------- gating via tensor-core HMMA -------------------
#define GLDM 136
#define SLDM 136
#define SM_W 0
#define SM_U (128 * GLDM)
#define SM_S_BYTES (2 * 128 * GLDM * 2)
#define GATE_SMEM (SM_S_BYTES + 128 * SLDM * 4)

__global__ void __launch_bounds__(256) gate_mma_kernel(const float* __restrict__ U,
                                                       const float* __restrict__ W4,
                                                       const float* __restrict__ B4,
                                                       __half* __restrict__ gate16) {
    extern __shared__ __half smh[];
    __half* Wsh = smh + SM_W;
    __half* Ush = smh + SM_U;
    float* St = (float*)((char*)smh + SM_S_BYTES);
    int tid = threadIdx.x;
    int warp = tid >> 5;
    int c = blockIdx.y;
    const float* W = W4 + c * DIMV * DIMV;
    __half* out16 = gate16 + (size_t)c * UF;

    for (int i = tid; i < DIMV * DIMV; i += 256) {
        int k = i >> 7, n = i & 127;
        Wsh[k * GLDM + n] = __float2half_rn(W[i]);
    }
    int ncol = tid & 127;
    float bias = B4[c * DIMV + ncol];

    for (int tile = blockIdx.x * 128; tile < NU; tile += gridDim.x * 128) {
        __syncthreads();
        for (int i = tid; i < 128 * DIMV; i += 256) {
            int r = i >> 7, n = i & 127;
            int gr = tile + r;
            float v = (gr < NU) ? U[(size_t)gr * DIMV + n] : 0.f;
            Ush[r * GLDM + n] = __float2half_rn(v);
        }
        __syncthreads();
        {
            wmma::fragment<wmma::accumulator, 16, 16, 16, float> fc[8];
#pragma unroll
            for (int n0 = 0; n0 < 8; n0++) wmma::fill_fragment(fc[n0], 0.f);
#pragma unroll
            for (int k0 = 0; k0 < 8; k0++) {
                wmma::fragment<wmma::matrix_a, 16, 16, 16, __half, wmma::row_major> fa;
                wmma::load_matrix_sync(fa, Ush + (warp * 16) * GLDM + k0 * 16, GLDM);
#pragma unroll
                for (int n0 = 0; n0 < 8; n0++) {
                    wmma::fragment<wmma::matrix_b, 16, 16, 16, __half, wmma::row_major> fb;
                    wmma::load_matrix_sync(fb, Wsh + (k0 * 16) * GLDM + n0 * 16, GLDM);
                    wmma::mma_sync(fc[n0], fa, fb, fc[n0]);
                }
            }
#pragma unroll
            for (int n0 = 0; n0 < 8; n0++)
                wmma::store_matrix_sync(St + (warp * 16) * SLDM + n0 * 16, fc[n0],
                                        SLDM, wmma::mem_row_major);
        }
        __syncthreads();
        for (int i = tid; i < 128 * DIMV; i += 256) {
            int r = i >> 7;
            int gr = tile + r;
            if (gr < NU) {
                float a = St[r * SLDM + ncol] + bias;
                float u = __half2float(Ush[r * GLDM + ncol]);
                out16[(size_t)gr * DIMV + ncol] = __float2half_rn(u / (1.f + expf(-a)));
            }
        }
    }
}

// ------------------- CSR build -------------------
struct BuildJob { const int* rows; const int* cols; const float* vals;
                  int* cnt; int* cur; int* offs; int2* pair; int ne; int nrows; };
struct Build5 { BuildJob j[5]; int bstart[6]; };

__device__ __forceinline__ int build_job_of(const Build5& a, int blk) {
    int k = 0;
#pragma unroll
    for (int q = 1; q < 5; q++) if (blk >= a.bstart[q]) k = q;
    return k;
}

__global__ void __launch_bounds__(256) count_kernel(Build5 a) {
    int k = build_job_of(a, blockIdx.x);
    BuildJob jb = a.j[k];
    int e = (blockIdx.x - a.bstart[k]) * 256 + threadIdx.x;
    if (e < jb.ne) atomicAdd(jb.cnt + __ldg(jb.rows + e), 1);
}

__global__ void __launch_bounds__(256) scan_chunks_kernel(Build5 a, int* __restrict__ aux) {
    BuildJob jb = a.j[blockIdx.y];
    int n = jb.nrows;
    int base = blockIdx.x * CHUNK;
    if (base >= n) return;
    int tid = threadIdx.x;
    int lane = tid & 31, wid = tid >> 5;
    int i = base + tid * 4;
    int4 v = make_int4(0, 0, 0, 0);
    if (i < n) v = *(const int4*)(jb.cnt + i);
    int s = v.x + v.y + v.z + v.w;
    int ss = s;
#pragma unroll
    for (int o = 1; o < 32; o <<= 1) { int tt = __shfl_up_sync(0xffffffffu, ss, o); if (lane >= o) ss += tt; }
    __shared__ int wsum[8];
    if (lane == 31) wsum[wid] = ss;
    __syncthreads();
    if (tid < 8) {
        int w = wsum[tid];
#pragma unroll
        for (int o = 1; o < 8; o <<= 1) { int tt = __shfl_up_sync(0xffu, w, o); if (tid >= o) w += tt; }
        wsum[tid] = w;
    }
    __syncthreads();
    int excl = ss - s + (wid ? wsum[wid - 1] : 0);
    if (i < n) {
        int4 e;
        e.x = excl; e.y = excl + v.x; e.z = e.y + v.y; e.w = e.z + v.z;
        *(int4*)(jb.offs + i) = e;
    }
    if (tid == 255) aux[blockIdx.y * 64 + blockIdx.x] = wsum[7];
}

__global__ void __launch_bounds__(160) scan_aux_kernel(Build5 a, int* __restrict__ aux) {
    int wid = threadIdx.x >> 5;
    if (wid >= 5) return;
    BuildJob jb = a.j[wid];
    int nch = (jb.nrows + CHUNK - 1) / CHUNK;
    int lane = threadIdx.x & 31;
    int carry = 0;
    for (int b0 = 0; b0 < nch; b0 += 32) {
        int idx = b0 + lane;
        int v = (idx < nch) ? aux[wid * 64 + idx] : 0;
        int s = v;
#pragma unroll
        for (int o = 1; o < 32; o <<= 1) { int tt = __shfl_up_sync(0xffffffffu, s, o); if (lane >= o) s += tt; }
        if (idx < nch) aux[wid * 64 + idx] = carry + s - v;
        carry += __shfl_sync(0xffffffffu, s, 31);
    }
    if (lane == 0) jb.offs[jb.nrows] = carry;
}

__global__ void __launch_bounds__(256) scan_apply_kernel(Build5 a, const int* __restrict__ aux) {
    BuildJob jb = a.j[blockIdx.y];
    int n = jb.nrows;
    int base = blockIdx.x * CHUNK;
    if (base >= n) return;
    int add = aux[blockIdx.y * 64 + blockIdx.x];
    int i = base + threadIdx.x * 4;
    if (i < n) {
        int4 e = *(const int4*)(jb.offs + i);
        e.x += add; e.y += add; e.z += add; e.w += add;
        *(int4*)(jb.offs + i) = e;
        *(int4*)(jb.cur + i) = e;
    }
}

__global__ void __launch_bounds__(256) scatter_kernel(Build5 a) {
    int k = build_job_of(a, blockIdx.x);
    BuildJob jb = a.j[k];
    int e = (blockIdx.x - a.bstart[k]) * 256 + threadIdx.x;
    if (e >= jb.ne) return;
    int r = __ldg(jb.rows + e);
    int p = atomicAdd(jb.cur + r, 1);
    jb.pair[p] = make_int2(__ldg(jb.cols + e), __float_as_int(__ldg(jb.vals + e)));
}

// ------------------- CSR SpMM (fp16 gathers), half-warp per row, unroll 8 -------------------
struct CsrJob { const int* offs; const int2* pair; const __half* X;
                __half* Y16; __half* Yn16; int nrows; };
struct Csr5 { CsrJob j[5]; int bstart[6]; };

__device__ __forceinline__ void fma_h8(float* acc, float v, uint4 raw) {
    float2 f0 = __half22float2(*(__half2*)&raw.x);
    float2 f1 = __half22float2(*(__half2*)&raw.y);
    float2 f2 = __half22float2(*(__half2*)&raw.z);
    float2 f3 = __half22float2(*(__half2*)&raw.w);
    acc[0] += v * f0.x; acc[1] += v * f0.y;
    acc[2] += v * f1.x; acc[3] += v * f1.y;
    acc[4] += v * f2.x; acc[5] += v * f2.y;
    acc[6] += v * f3.x; acc[7] += v * f3.y;
}

__global__ void __launch_bounds__(256) spmm_csr5_kernel(Csr5 a) {
    int blk = blockIdx.x;
    int k = 0;
#pragma unroll
    for (int q = 1; q < 5; q++) if (blk >= a.bstart[q]) k = q;
    CsrJob jb = a.j[k];
    int lane = threadIdx.x & 31;
    int hl = lane & 15;
    int side = lane >> 4;
    int warp = threadIdx.x >> 5;
    int w = (blk - a.bstart[k]) * 16 + warp * 2 + side;
    unsigned hmask = 0xFFFFu << (side * 16);
    if (w >= jb.nrows) return;
    int start = __ldg(jb.offs + w);
    int end = __ldg(jb.offs + w + 1);
    float acc[8];
#pragma unroll
    for (int q = 0; q < 8; q++) acc[q] = 0.f;
    const __half* X = jb.X;
    for (int b = start; b < end; b += 16) {
        int i = b + hl;
        int c = 0; float v = 0.f;
        if (i < end) { int2 pr = __ldg(jb.pair + i); c = pr.x; v = __int_as_float(pr.y); }
        int m = end - b; if (m > 16) m = 16;
        int j = 0;
        for (; j + 8 <= m; j += 8) {
            int cc[8]; float vv[8];
#pragma unroll
            for (int q = 0; q < 8; q++) {
                cc[q] = __shfl_sync(hmask, c, j + q, 16);
                vv[q] = __shfl_sync(hmask, v, j + q, 16);
            }
            uint4 xx[8];
#pragma unroll
            for (int q = 0; q < 8; q++)
                xx[q] = __ldg((const uint4*)(X + (size_t)cc[q] * DIMV) + hl);
#pragma unroll
            for (int q = 0; q < 8; q++)
                fma_h8(acc, vv[q], xx[q]);
        }
        for (; j + 4 <= m; j += 4) {
            int c0 = __shfl_sync(hmask, c, j + 0, 16);
            int c1 = __shfl_sync(hmask, c, j + 1, 16);
            int c2 = __shfl_sync(hmask, c, j + 2, 16);
            int c3 = __shfl_sync(hmask, c, j + 3, 16);
            uint4 x0 = __ldg((const uint4*)(X + (size_t)c0 * DIMV) + hl);
            uint4 x1 = __ldg((const uint4*)(X + (size_t)c1 * DIMV) + hl);
            uint4 x2 = __ldg((const uint4*)(X + (size_t)c2 * DIMV) + hl);
            uint4 x3 = __ldg((const uint4*)(X + (size_t)c3 * DIMV) + hl);
            float v0 = __shfl_sync(hmask, v, j + 0, 16);
            float v1 = __shfl_sync(hmask, v, j + 1, 16);
            float v2 = __shfl_sync(hmask, v, j + 2, 16);
            float v3 = __shfl_sync(hmask, v, j + 3, 16);
            fma_h8(acc, v0, x0);
            fma_h8(acc, v1, x1);
            fma_h8(acc, v2, x2);
            fma_h8(acc, v3, x3);
        }
        for (; j < m; j++) {
            int cj = __shfl_sync(hmask, c, j, 16);
            float vj = __shfl_sync(hmask, v, j, 16);
            uint4 x = __ldg((const uint4*)(X + (size_t)cj * DIMV) + hl);
            fma_h8(acc, vj, x);
        }
    }
    size_t base = (size_t)w * DIMV + hl * 8;
    if (jb.Y16) {
        union { __half2 h[4]; uint4 u; } cv;
        cv.h[0] = __floats2half2_rn(acc[0], acc[1]);
        cv.h[1] = __floats2half2_rn(acc[2], acc[3]);
        cv.h[2] = __floats2half2_rn(acc[4], acc[5]);
        cv.h[3] = __floats2half2_rn(acc[6], acc[7]);
        *(uint4*)(jb.Y16 + base) = cv.u;
    }
    if (jb.Yn16) {
        float ss = 0.f;
#pragma unroll
        for (int q = 0; q < 8; q++) ss += acc[q] * acc[q];
#pragma unroll
        for (int o = 8; o; o >>= 1) ss += __shfl_xor_sync(hmask, ss, o, 16);
        float sc = rsqrtf(fmaxf(ss, 1e-12f));
        union { __half2 h[4]; uint4 u; } cv;
        cv.h[0] = __floats2half2_rn(acc[0] * sc, acc[1] * sc);
        cv.h[1] = __floats2half2_rn(acc[2] * sc, acc[3] * sc);
        cv.h[2] = __floats2half2_rn(acc[4] * sc, acc[5] * sc);
        cv.h[3] = __floats2half2_rn(acc[6] * sc, acc[7] * sc);
        *(uint4*)(jb.Yn16 + base) = cv.u;
    }
}

// ------------------- helpers -------------------
__device__ __forceinline__ float4 ldh4(const __half* p) {
    uint2 r = *(const uint2*)p;
    float2 f0 = __half22float2(*(__half2*)&r.x);
    float2 f1 = __half22float2(*(__half2*)&r.y);
    return make_float4(f0.x, f0.y, f1.x, f1.y);
}

// ------------------- mix (fp16 inputs) -> fp16 out -------------------
__global__ void __launch_bounds__(256) mix_h_kernel(
        const __half* __restrict__ C0, const __half* __restrict__ C1, const __half* __restrict__ C2,
        const __half* __restrict__ S, __half* __restrict__ out16, int nrows) {
    int w = (int)((blockIdx.x * (unsigned)blockDim.x + threadIdx.x) >> 5);
    int lane = threadIdx.x & 31;
    if (w >= nrows) return;
    size_t base = (size_t)w * DIMV + lane * 4;
    float4 v = *(const float4*)(g_attvec + lane * 4);
    float4 c0 = ldh4(C0 + base);
    float4 c1 = ldh4(C1 + base);
    float4 c2 = ldh4(C2 + base);
    float w0 = c0.x * v.x + c0.y * v.y + c0.z * v.z + c0.w * v.w;
    float w1 = c1.x * v.x + c1.y * v.y + c1.z * v.z + c1.w * v.w;
    float w2 = c2.x * v.x + c2.y * v.y + c2.z * v.z + c2.w * v.w;
#pragma unroll
    for (int o = 16; o; o >>= 1) {
        w0 += __shfl_xor_sync(0xffffffffu, w0, o);
        w1 += __shfl_xor_sync(0xffffffffu, w1, o);
        w2 += __shfl_xor_sync(0xffffffffu, w2, o);
    }
    float m = fmaxf(w0, fmaxf(w1, w2));
    float e0 = expf(w0 - m), e1 = expf(w1 - m), e2 = expf(w2 - m);
    float inv = 1.f / (e0 + e1 + e2);
    e0 *= inv; e1 *= inv; e2 *= inv;
    float4 s = ldh4(S + base);
    float4 o;
    o.x = e0 * c0.x + e1 * c1.x + e2 * c2.x + 0.5f * s.x;
    o.y = e0 * c0.y + e1 * c1.y + e2 * c2.y + 0.5f * s.y;
    o.z = e0 * c0.z + e1 * c1.z + e2 * c2.z + 0.5f * s.z;
    o.w = e0 * c0.w + e1 * c1.w + e2 * c2.w + 0.5f * s.w;
    union { __half2 h[2]; uint2 u; } cv;
    cv.h[0] = __floats2half2_rn(o.x, o.y);
    cv.h[1] = __floats2half2_rn(o.z, o.w);
    *(uint2*)(out16 + base) = cv.u;
}

// ------------------- final mix: C_k = g_k + n1_k + n2_k; S = g3 + s1n + s2n -------------------
__global__ void __launch_bounds__(256) mix_final_kernel(
        const __half* __restrict__ gate16, const __half* __restrict__ n1,
        const __half* __restrict__ n2, const __half* __restrict__ s1n,
        const __half* __restrict__ s2n, float* __restrict__ out, int nrows) {
    int w = (int)((blockIdx.x * (unsigned)blockDim.x + threadIdx.x) >> 5);
    int lane = threadIdx.x & 31;
    if (w >= nrows) return;
    size_t base = (size_t)w * DIMV + lane * 4;
    float4 v = *(const float4*)(g_attvec + lane * 4);
    float4 c[3];
#pragma unroll
    for (int k = 0; k < 3; k++) {
        float4 g = ldh4(gate16 + (size_t)k * UF + base);
        float4 a = ldh4(n1 + (size_t)k * UF + base);
        float4 n = ldh4(n2 + (size_t)k * UF + base);
        c[k].x = g.x + a.x + n.x;
        c[k].y = g.y + a.y + n.y;
        c[k].z = g.z + a.z + n.z;
        c[k].w = g.w + a.w + n.w;
    }
    float w0 = c[0].x * v.x + c[0].y * v.y + c[0].z * v.z + c[0].w * v.w;
    float w1 = c[1].x * v.x + c[1].y * v.y + c[1].z * v.z + c[1].w * v.w;
    float w2 = c[2].x * v.x + c[2].y * v.y + c[2].z * v.z + c[2].w * v.w;
#pragma unroll
    for (int o = 16; o; o >>= 1) {
        w0 += __shfl_xor_sync(0xffffffffu, w0, o);
        w1 += __shfl_xor_sync(0xffffffffu, w1, o);
        w2 += __shfl_xor_sync(0xffffffffu, w2, o);
    }
    float m = fmaxf(w0, fmaxf(w1, w2));
    float e0 = expf(w0 - m), e1 = expf(w1 - m), e2 = expf(w2 - m);
    float inv = 1.f / (e0 + e1 + e2);
    e0 *= inv; e1 *= inv; e2 *= inv;
    float4 g3 = ldh4(gate16 + 3 * UF + base);
    float4 sa = ldh4(s1n + base);
    float4 sn = ldh4(s2n + base);
    float4 o;
    o.x = e0 * c[0].x + e1 * c[1].x + e2 * c[2].x + 0.5f * (g3.x + sa.x + sn.x);
    o.y = e0 * c[0].y + e1 * c[1].y + e2 * c[2].y + 0.5f * (g3.y + sa.y + sn.y);
    o.z = e0 * c[0].z + e1 * c[1].z + e2 * c[2].z + 0.5f * (g3.z + sa.z + sn.z);
    o.w = e0 * c[0].w + e1 * c[1].w + e2 * c[2].w + 0.5f * (g3.w + sa.w + sn.w);
    *(float4*)(out + base) = o;
}

// ------------------- item output: out = i_emb + i1n + i2n -------------------
__global__ void __launch_bounds__(256) item_out_kernel(const float* __restrict__ ie,
                                                       const __half* __restrict__ i1n,
                                                       const __half* __restrict__ i2n,
                                                       float* __restrict__ out) {
    int i = blockIdx.x * blockDim.x + threadIdx.x;
    if (i < (int)(IFl / 4)) {
        float4 a = __ldg((const float4*)ie + i);
        float4 b = ldh4(i1n + (size_t)i * 4);
        float4 n = ldh4(i2n + (size_t)i * 4);
        a.x += b.x + n.x; a.y += b.y + n.y; a.z += b.z + n.z; a.w += b.w + n.w;
        *((float4*)out + i) = a;
    }
}

// ------------------- host orchestration -------------------
extern "C" void kernel_launch(void* const* d_in, const int* in_sizes, int n_in,
                              void* d_out, int out_size) {
    const float* u_emb = (const float*)d_in[0];
    const float* i_emb = (const float*)d_in[1];
    const float* gW = (const float*)d_in[2];
    const float* gB = (const float*)d_in[3];
    const float* att = (const float*)d_in[4];
    const float* attm = (const float*)d_in[5];
    const int* Hr[3] = {(const int*)d_in[6], (const int*)d_in[9], (const int*)d_in[12]};
    const int* Hc[3] = {(const int*)d_in[7], (const int*)d_in[10], (const int*)d_in[13]};
    const float* Hv[3] = {(const float*)d_in[8], (const float*)d_in[11], (const float*)d_in[14]};
    const int* Rr = (const int*)d_in[15];
    const int* Rc = (const int*)d_in[16];
    const float* Rv = (const float*)d_in[17];
    int EH = in_sizes[6], ER = in_sizes[15];
    float* out = (float*)d_out;

    static __half* H = nullptr;
    static int *cnt = nullptr, *cur = nullptr, *offs = nullptr, *aux = nullptr;
    static int2* pair = nullptr;
    static cudaStream_t s2 = nullptr;
    static cudaEvent_t evFork = nullptr, evJoin = nullptr;
    if (!H) {
        cudaGetSymbolAddress((void**)&H, g_hbuf);
        cudaGetSymbolAddress((void**)&cnt, g_cnt);
        cudaGetSymbolAddress((void**)&cur, g_cur);
        cudaGetSymbolAddress((void**)&offs, g_offs);
        cudaGetSymbolAddress((void**)&pair, g_pair);
        cudaGetSymbolAddress((void**)&aux, g_aux);
        cudaFuncSetAttribute(gate_mma_kernel, cudaFuncAttributeMaxDynamicSharedMemorySize, GATE_SMEM);
        cudaStreamCreateWithFlags(&s2, cudaStreamNonBlocking);
        cudaEventCreateWithFlags(&evFork, cudaEventDisableTiming);
        cudaEventCreateWithFlags(&evJoin, cudaEventDisableTiming);
    }
    __half* gate16 = H + H_GATE;
    __half* curA16 = H + H_CURA;
    __half* mix16 = H + H_MIX;
    __half* s1_16 = H + H_S1;
    __half* n1_16 = H + H_N1;
    __half* n2_16 = H + H_N2;
    __half* s1n16 = H + H_S1N;
    __half* s2n16 = H + H_S2N;
    __half* i1_16 = H + H_I1;
    __half* i1n16 = H + H_I1N;
    __half* i2n16 = H + H_I2N;
    __half* iemb16 = H + H_IEMB;

#define GP16(c) (gate16 + (size_t)(c) * UF)
#define CA16(c) (curA16 + (size_t)(c) * UF)
#define N1(c) (n1_16 + (size_t)(c) * UF)
#define N2(c) (n2_16 + (size_t)(c) * UF)

    Build5 bj;
    for (int k = 0; k < 3; k++)
        bj.j[k] = {Hr[k], Hc[k], Hv[k], cnt + k * NU, cur + k * NU, offs + k * OSTR,
                   pair + (size_t)k * EHMAX, EH, NU};
    bj.j[3] = {Rr, Rc, Rv, cnt + 3 * NU, cur + 3 * NU, offs + 3 * OSTR,
               pair + 3 * (size_t)EHMAX, ER, NU};
    bj.j[4] = {Rc, Rr, Rv, cnt + 4 * NU, cur + 4 * NU, offs + 4 * OSTR,
               pair + 3 * (size_t)EHMAX + ERMAX, ER, NI};
    {
        int be[5];
        for (int k = 0; k < 5; k++) be[k] = (bj.j[k].ne + 255) / 256;
        bj.bstart[0] = 0;
        for (int k = 0; k < 5; k++) bj.bstart[k + 1] = bj.bstart[k] + be[k];
    }

    const int* offsR = bj.j[3].offs;  const int2* pairR = bj.j[3].pair;
    const int* offsRT = bj.j[4].offs; const int2* pairRT = bj.j[4].pair;

    // ---- fork: CSR build on s2, dense prologue on main ----
    cudaEventRecord(evFork, 0);
    cudaStreamWaitEvent(s2, evFork, 0);

    cudaMemsetAsync(cnt, 0, CNT_TOT * sizeof(int), s2);
    count_kernel<<<bj.bstart[5], 256, 0, s2>>>(bj);
    scan_chunks_kernel<<<dim3(NCHU, 5), 256, 0, s2>>>(bj, aux);
    scan_aux_kernel<<<1, 160, 0, s2>>>(bj, aux);
    scan_apply_kernel<<<dim3(NCHU, 5), 256, 0, s2>>>(bj, aux);
    scatter_kernel<<<bj.bstart[5], 256, 0, s2>>>(bj);
    cudaEventRecord(evJoin, s2);

    attvec_kernel<<<1, 128>>>(att, attm);
    f2h_kernel<<<(int)((IFl / 4 + 255) / 256), 256>>>(i_emb, iemb16, (int)(IFl / 4));
    gate_mma_kernel<<<dim3(148, 4), 256, GATE_SMEM>>>(u_emb, gW, gB, gate16);

    int mixb = (NU + 7) / 8;
    const int BU = (NU + 15) / 16;
    const int BI = (NI + 15) / 16;

    mix_h_kernel<<<mixb, 256>>>(GP16(0), GP16(1), GP16(2), GP16(3), mix16, NU);

    cudaStreamWaitEvent(0, evJoin, 0);   // join before SpMM

    // ---------------- layer 1: raw fp16 out + fp16 l2norm write ----------------
    {
        Csr5 a;
        for (int k = 0; k < 3; k++)
            a.j[k] = {bj.j[k].offs, bj.j[k].pair, GP16(k), CA16(k), N1(k), NU};
        a.j[3] = {offsRT, pairRT, mix16, i1_16, i1n16, NI};  // item1 = R^T @ mixed
        a.j[4] = {offsR, pairR, iemb16, s1_16, s1n16, NU};   // s1 = R @ i_emb
        a.bstart[0] = 0; a.bstart[1] = BU; a.bstart[2] = 2 * BU; a.bstart[3] = 3 * BU;
        a.bstart[4] = 3 * BU + BI; a.bstart[5] = 4 * BU + BI;
        spmm_csr5_kernel<<<a.bstart[5], 256>>>(a);
    }

    // ---------------- layer 2: fp16 l2norm only ----------------
    mix_h_kernel<<<mixb, 256>>>(CA16(0), CA16(1), CA16(2), s1_16, mix16, NU);
    {
        Csr5 a;
        for (int k = 0; k < 3; k++)
            a.j[k] = {bj.j[k].offs, bj.j[k].pair, CA16(k), nullptr, N2(k), NU};
        a.j[3] = {offsRT, pairRT, mix16, nullptr, i2n16, NI};  // l2n(R^T @ mixed2)
        a.j[4] = {offsR, pairR, i1_16, nullptr, s2n16, NU};    // l2n(R @ item1)
        a.bstart[0] = 0; a.bstart[1] = BU; a.bstart[2] = 2 * BU; a.bstart[3] = 3 * BU;
        a.bstart[4] = 3 * BU + BI; a.bstart[5] = 4 * BU + BI;
        spmm_csr5_kernel<<<a.bstart[5], 256>>>(a);
    }

    // ---------------- final ----------------
    mix_final_kernel<<<mixb, 256>>>(gate16, n1_16, n2_16, s1n16, s2n16, out, NU);
    item_out_kernel<<<(int)((IFl / 4 + 255) / 256), 256>>>(i_emb, i1n16, i2n16,
                                                           out + (size_t)NU * DIMV);
}

// round 16
// speedup vs baseline: 1.1220x; 1.1220x over previous
#include <cuda_runtime.h>
#include <cuda_fp16.h>
#include <mma.h>
#include <cstdint>

using namespace nvcuda;

#define NU 50000
#define NI 25000
#define DIMV 128
#define EHMAX 600000
#define ERMAX 1000000
#define CHUNK 1024
#define NCHU 49
#define OSTR 50016

#define UF ((size_t)NU * DIMV)
#define IFl ((size_t)NI * DIMV)

// ------------------- fp16 scratch (everything) -------------------
#define H_GATE ((size_t)0)          // 4 channels
#define H_CURA (4 * UF)             // 3 channels, layer-1 H outputs (raw)
#define H_MIX  (7 * UF)
#define H_S1   (8 * UF)
#define H_N1   (9 * UF)             // 3 channels, l2n(layer-1 H outputs)
#define H_N2   (12 * UF)            // 3 channels, l2n(layer-2 H outputs)
#define H_S1N  (15 * UF)            // l2n(layer-1 R output)
#define H_S2N  (16 * UF)            // l2n(layer-2 R output)
#define H_I1   (17 * UF)
#define H_I1N  (17 * UF + IFl)      // l2n(layer-1 RT output)
#define H_I2N  (17 * UF + 2 * IFl)  // l2n(layer-2 RT output)
#define H_IEMB (17 * UF + 3 * IFl)
#define TOTALH (17 * UF + 4 * IFl)
__device__ __align__(16) __half g_hbuf[TOTALH];

__device__ float g_attvec[DIMV];

// ------------------- CSR scratch -------------------
#define CNT_TOT (4 * NU + NI)
#define OFFS_TOT (4 * OSTR + NI + 16)
#define PE_TOT (3 * EHMAX + 2 * ERMAX)
__device__ __align__(16) int g_cnt[CNT_TOT];
__device__ __align__(16) int g_cur[CNT_TOT];
__device__ __align__(16) int g_offs[OFFS_TOT];
__device__ __align__(16) int2 g_pair[PE_TOT];
__device__ int g_aux[5 * 64];

// ------------------- attention vector: v = M @ a -------------------
__global__ void attvec_kernel(const float* __restrict__ att, const float* __restrict__ mat) {
    int j = threadIdx.x;
    float s = 0.f;
#pragma unroll 8
    for (int d = 0; d < DIMV; d++) s += mat[j * DIMV + d] * att[d];
    g_attvec[j] = s;
}

// ------------------- f32 -> f16 conversion -------------------
__global__ void __launch_bounds__(256) f2h_kernel(const float* __restrict__ src,
                                                  __half* __restrict__ dst, int n4) {
    int i = blockIdx.x * 256 + threadIdx.x;
    if (i < n4) {
        float4 v = __ldg((const float4*)src + i);
        union { __half2 h[2]; uint2 u; } cv;
        cv.h[0] = __floats2half2_rn(v.x, v.y);
        cv.h[1] = __floats2half2_rn(v.z, v.w);
        *(uint2*)(dst + (size_t)i * 4) = cv.u;
    }
}

// ------------------- gating via tensor-core HMMA -------------------
#define GLDM 136
#define SLDM 136
#define SM_W 0
#define SM_U (128 * GLDM)
#define SM_S_BYTES (2 * 128 * GLDM * 2)
#define GATE_SMEM (SM_S_BYTES + 128 * SLDM * 4)

__global__ void __launch_bounds__(256) gate_mma_kernel(const float* __restrict__ U,
                                                       const float* __restrict__ W4,
                                                       const float* __restrict__ B4,
                                                       __half* __restrict__ gate16) {
    extern __shared__ __half smh[];
    __half* Wsh = smh + SM_W;
    __half* Ush = smh + SM_U;
    float* St = (float*)((char*)smh + SM_S_BYTES);
    int tid = threadIdx.x;
    int warp = tid >> 5;
    int c = blockIdx.y;
    const float* W = W4 + c * DIMV * DIMV;
    __half* out16 = gate16 + (size_t)c * UF;

    for (int i = tid; i < DIMV * DIMV; i += 256) {
        int k = i >> 7, n = i & 127;
        Wsh[k * GLDM + n] = __float2half_rn(W[i]);
    }
    int ncol = tid & 127;
    float bias = B4[c * DIMV + ncol];

    for (int tile = blockIdx.x * 128; tile < NU; tile += gridDim.x * 128) {
        __syncthreads();
        for (int i = tid; i < 128 * DIMV; i += 256) {
            int r = i >> 7, n = i & 127;
            int gr = tile + r;
            float v = (gr < NU) ? U[(size_t)gr * DIMV + n] : 0.f;
            Ush[r * GLDM + n] = __float2half_rn(v);
        }
        __syncthreads();
        {
            wmma::fragment<wmma::accumulator, 16, 16, 16, float> fc[8];
#pragma unroll
            for (int n0 = 0; n0 < 8; n0++) wmma::fill_fragment(fc[n0], 0.f);
#pragma unroll
            for (int k0 = 0; k0 < 8; k0++) {
                wmma::fragment<wmma::matrix_a, 16, 16, 16, __half, wmma::row_major> fa;
                wmma::load_matrix_sync(fa, Ush + (warp * 16) * GLDM + k0 * 16, GLDM);
#pragma unroll
                for (int n0 = 0; n0 < 8; n0++) {
                    wmma::fragment<wmma::matrix_b, 16, 16, 16, __half, wmma::row_major> fb;
                    wmma::load_matrix_sync(fb, Wsh + (k0 * 16) * GLDM + n0 * 16, GLDM);
                    wmma::mma_sync(fc[n0], fa, fb, fc[n0]);
                }
            }
#pragma unroll
            for (int n0 = 0; n0 < 8; n0++)
                wmma::store_matrix_sync(St + (warp * 16) * SLDM + n0 * 16, fc[n0],
                                        SLDM, wmma::mem_row_major);
        }
        __syncthreads();
        for (int i = tid; i < 128 * DIMV; i += 256) {
            int r = i >> 7;
            int gr = tile + r;
            if (gr < NU) {
                float a = St[r * SLDM + ncol] + bias;
                float u = __half2float(Ush[r * GLDM + ncol]);
                out16[(size_t)gr * DIMV + ncol] = __float2half_rn(u / (1.f + expf(-a)));
            }
        }
    }
}

// ------------------- CSR build -------------------
struct BuildJob { const int* rows; const int* cols; const float* vals;
                  int* cnt; int* cur; int* offs; int2* pair; int ne; int nrows; };
struct Build5 { BuildJob j[5]; int bstart[6]; };

__device__ __forceinline__ int build_job_of(const Build5& a, int blk) {
    int k = 0;
#pragma unroll
    for (int q = 1; q < 5; q++) if (blk >= a.bstart[q]) k = q;
    return k;
}

__global__ void __launch_bounds__(256) count_kernel(Build5 a) {
    int k = build_job_of(a, blockIdx.x);
    BuildJob jb = a.j[k];
    int e = (blockIdx.x - a.bstart[k]) * 256 + threadIdx.x;
    if (e < jb.ne) atomicAdd(jb.cnt + __ldg(jb.rows + e), 1);
}

__global__ void __launch_bounds__(256) scan_chunks_kernel(Build5 a, int* __restrict__ aux) {
    BuildJob jb = a.j[blockIdx.y];
    int n = jb.nrows;
    int base = blockIdx.x * CHUNK;
    if (base >= n) return;
    int tid = threadIdx.x;
    int lane = tid & 31, wid = tid >> 5;
    int i = base + tid * 4;
    int4 v = make_int4(0, 0, 0, 0);
    if (i < n) v = *(const int4*)(jb.cnt + i);
    int s = v.x + v.y + v.z + v.w;
    int ss = s;
#pragma unroll
    for (int o = 1; o < 32; o <<= 1) { int tt = __shfl_up_sync(0xffffffffu, ss, o); if (lane >= o) ss += tt; }
    __shared__ int wsum[8];
    if (lane == 31) wsum[wid] = ss;
    __syncthreads();
    if (tid < 8) {
        int w = wsum[tid];
#pragma unroll
        for (int o = 1; o < 8; o <<= 1) { int tt = __shfl_up_sync(0xffu, w, o); if (tid >= o) w += tt; }
        wsum[tid] = w;
    }
    __syncthreads();
    int excl = ss - s + (wid ? wsum[wid - 1] : 0);
    if (i < n) {
        int4 e;
        e.x = excl; e.y = excl + v.x; e.z = e.y + v.y; e.w = e.z + v.z;
        *(int4*)(jb.offs + i) = e;
    }
    if (tid == 255) aux[blockIdx.y * 64 + blockIdx.x] = wsum[7];
}

__global__ void __launch_bounds__(160) scan_aux_kernel(Build5 a, int* __restrict__ aux) {
    int wid = threadIdx.x >> 5;
    if (wid >= 5) return;
    BuildJob jb = a.j[wid];
    int nch = (jb.nrows + CHUNK - 1) / CHUNK;
    int lane = threadIdx.x & 31;
    int carry = 0;
    for (int b0 = 0; b0 < nch; b0 += 32) {
        int idx = b0 + lane;
        int v = (idx < nch) ? aux[wid * 64 + idx] : 0;
        int s = v;
#pragma unroll
        for (int o = 1; o < 32; o <<= 1) { int tt = __shfl_up_sync(0xffffffffu, s, o); if (lane >= o) s += tt; }
        if (idx < nch) aux[wid * 64 + idx] = carry + s - v;
        carry += __shfl_sync(0xffffffffu, s, 31);
    }
    if (lane == 0) jb.offs[jb.nrows] = carry;
}

__global__ void __launch_bounds__(256) scan_apply_kernel(Build5 a, const int* __restrict__ aux) {
    BuildJob jb = a.j[blockIdx.y];
    int n = jb.nrows;
    int base = blockIdx.x * CHUNK;
    if (base >= n) return;
    int add = aux[blockIdx.y * 64 + blockIdx.x];
    int i = base + threadIdx.x * 4;
    if (i < n) {
        int4 e = *(const int4*)(jb.offs + i);
        e.x += add; e.y += add; e.z += add; e.w += add;
        *(int4*)(jb.offs + i) = e;
        *(int4*)(jb.cur + i) = e;
    }
}

__global__ void __launch_bounds__(256) scatter_kernel(Build5 a) {
    int k = build_job_of(a, blockIdx.x);
    BuildJob jb = a.j[k];
    int e = (blockIdx.x - a.bstart[k]) * 256 + threadIdx.x;
    if (e >= jb.ne) return;
    int r = __ldg(jb.rows + e);
    int p = atomicAdd(jb.cur + r, 1);
    jb.pair[p] = make_int2(__ldg(jb.cols + e), __float_as_int(__ldg(jb.vals + e)));
}

// ------------------- CSR SpMM (fp16 gathers), half-warp per row (4-wide batches) -------------------
struct CsrJob { const int* offs; const int2* pair; const __half* X;
                __half* Y16; __half* Yn16; int nrows; };
struct Csr5 { CsrJob j[5]; int bstart[6]; };

__device__ __forceinline__ void fma_h8(float* acc, float v, uint4 raw) {
    float2 f0 = __half22float2(*(__half2*)&raw.x);
    float2 f1 = __half22float2(*(__half2*)&raw.y);
    float2 f2 = __half22float2(*(__half2*)&raw.z);
    float2 f3 = __half22float2(*(__half2*)&raw.w);
    acc[0] += v * f0.x; acc[1] += v * f0.y;
    acc[2] += v * f1.x; acc[3] += v * f1.y;
    acc[4] += v * f2.x; acc[5] += v * f2.y;
    acc[6] += v * f3.x; acc[7] += v * f3.y;
}

__global__ void __launch_bounds__(256) spmm_csr5_kernel(Csr5 a) {
    int blk = blockIdx.x;
    int k = 0;
#pragma unroll
    for (int q = 1; q < 5; q++) if (blk >= a.bstart[q]) k = q;
    CsrJob jb = a.j[k];
    int lane = threadIdx.x & 31;
    int hl = lane & 15;
    int side = lane >> 4;
    int warp = threadIdx.x >> 5;
    int w = (blk - a.bstart[k]) * 16 + warp * 2 + side;
    unsigned hmask = 0xFFFFu << (side * 16);
    if (w >= jb.nrows) return;
    int start = __ldg(jb.offs + w);
    int end = __ldg(jb.offs + w + 1);
    float acc[8];
#pragma unroll
    for (int q = 0; q < 8; q++) acc[q] = 0.f;
    const __half* X = jb.X;
    for (int b = start; b < end; b += 16) {
        int i = b + hl;
        int c = 0; float v = 0.f;
        if (i < end) { int2 pr = __ldg(jb.pair + i); c = pr.x; v = __int_as_float(pr.y); }
        int m = end - b; if (m > 16) m = 16;
        int j = 0;
        for (; j + 4 <= m; j += 4) {
            int c0 = __shfl_sync(hmask, c, j + 0, 16);
            int c1 = __shfl_sync(hmask, c, j + 1, 16);
            int c2 = __shfl_sync(hmask, c, j + 2, 16);
            int c3 = __shfl_sync(hmask, c, j + 3, 16);
            uint4 x0 = __ldg((const uint4*)(X + (size_t)c0 * DIMV) + hl);
            uint4 x1 = __ldg((const uint4*)(X + (size_t)c1 * DIMV) + hl);
            uint4 x2 = __ldg((const uint4*)(X + (size_t)c2 * DIMV) + hl);
            uint4 x3 = __ldg((const uint4*)(X + (size_t)c3 * DIMV) + hl);
            float v0 = __shfl_sync(hmask, v, j + 0, 16);
            float v1 = __shfl_sync(hmask, v, j + 1, 16);
            float v2 = __shfl_sync(hmask, v, j + 2, 16);
            float v3 = __shfl_sync(hmask, v, j + 3, 16);
            fma_h8(acc, v0, x0);
            fma_h8(acc, v1, x1);
            fma_h8(acc, v2, x2);
            fma_h8(acc, v3, x3);
        }
        for (; j < m; j++) {
            int cj = __shfl_sync(hmask, c, j, 16);
            float vj = __shfl_sync(hmask, v, j, 16);
            uint4 x = __ldg((const uint4*)(X + (size_t)cj * DIMV) + hl);
            fma_h8(acc, vj, x);
        }
    }
    size_t base = (size_t)w * DIMV + hl * 8;
    if (jb.Y16) {
        union { __half2 h[4]; uint4 u; } cv;
        cv.h[0] = __floats2half2_rn(acc[0], acc[1]);
        cv.h[1] = __floats2half2_rn(acc[2], acc[3]);
        cv.h[2] = __floats2half2_rn(acc[4], acc[5]);
        cv.h[3] = __floats2half2_rn(acc[6], acc[7]);
        *(uint4*)(jb.Y16 + base) = cv.u;
    }
    if (jb.Yn16) {
        float ss = 0.f;
#pragma unroll
        for (int q = 0; q < 8; q++) ss += acc[q] * acc[q];
#pragma unroll
        for (int o = 8; o; o >>= 1) ss += __shfl_xor_sync(hmask, ss, o, 16);
        float sc = rsqrtf(fmaxf(ss, 1e-12f));
        union { __half2 h[4]; uint4 u; } cv;
        cv.h[0] = __floats2half2_rn(acc[0] * sc, acc[1] * sc);
        cv.h[1] = __floats2half2_rn(acc[2] * sc, acc[3] * sc);
        cv.h[2] = __floats2half2_rn(acc[4] * sc, acc[5] * sc);
        cv.h[3] = __floats2half2_rn(acc[6] * sc, acc[7] * sc);
        *(uint4*)(jb.Yn16 + base) = cv.u;
    }
}

// ------------------- helpers -------------------
__device__ __forceinline__ float4 ldh4(const __half* p) {
    uint2 r = *(const uint2*)p;
    float2 f0 = __half22float2(*(__half2*)&r.x);
    float2 f1 = __half22float2(*(__half2*)&r.y);
    return make_float4(f0.x, f0.y, f1.x, f1.y);
}

// ------------------- mix (fp16 inputs) -> fp16 out -------------------
__global__ void __launch_bounds__(256) mix_h_kernel(
        const __half* __restrict__ C0, const __half* __restrict__ C1, const __half* __restrict__ C2,
        const __half* __restrict__ S, __half* __restrict__ out16, int nrows) {
    int w = (int)((blockIdx.x * (unsigned)blockDim.x + threadIdx.x) >> 5);
    int lane = threadIdx.x & 31;
    if (w >= nrows) return;
    size_t base = (size_t)w * DIMV + lane * 4;
    float4 v = *(const float4*)(g_attvec + lane * 4);
    float4 c0 = ldh4(C0 + base);
    float4 c1 = ldh4(C1 + base);
    float4 c2 = ldh4(C2 + base);
    float w0 = c0.x * v.x + c0.y * v.y + c0.z * v.z + c0.w * v.w;
    float w1 = c1.x * v.x + c1.y * v.y + c1.z * v.z + c1.w * v.w;
    float w2 = c2.x * v.x + c2.y * v.y + c2.z * v.z + c2.w * v.w;
#pragma unroll
    for (int o = 16; o; o >>= 1) {
        w0 += __shfl_xor_sync(0xffffffffu, w0, o);
        w1 += __shfl_xor_sync(0xffffffffu, w1, o);
        w2 += __shfl_xor_sync(0xffffffffu, w2, o);
    }
    float m = fmaxf(w0, fmaxf(w1, w2));
    float e0 = expf(w0 - m), e1 = expf(w1 - m), e2 = expf(w2 - m);
    float inv = 1.f / (e0 + e1 + e2);
    e0 *= inv; e1 *= inv; e2 *= inv;
    float4 s = ldh4(S + base);
    float4 o;
    o.x = e0 * c0.x + e1 * c1.x + e2 * c2.x + 0.5f * s.x;
    o.y = e0 * c0.y + e1 * c1.y + e2 * c2.y + 0.5f * s.y;
    o.z = e0 * c0.z + e1 * c1.z + e2 * c2.z + 0.5f * s.z;
    o.w = e0 * c0.w + e1 * c1.w + e2 * c2.w + 0.5f * s.w;
    union { __half2 h[2]; uint2 u; } cv;
    cv.h[0] = __floats2half2_rn(o.x, o.y);
    cv.h[1] = __floats2half2_rn(o.z, o.w);
    *(uint2*)(out16 + base) = cv.u;
}

// ------------------- final mix: C_k = g_k + n1_k + n2_k; S = g3 + s1n + s2n -------------------
__global__ void __launch_bounds__(256) mix_final_kernel(
        const __half* __restrict__ gate16, const __half* __restrict__ n1,
        const __half* __restrict__ n2, const __half* __restrict__ s1n,
        const __half* __restrict__ s2n, float* __restrict__ out, int nrows) {
    int w = (int)((blockIdx.x * (unsigned)blockDim.x + threadIdx.x) >> 5);
    int lane = threadIdx.x & 31;
    if (w >= nrows) return;
    size_t base = (size_t)w * DIMV + lane * 4;
    float4 v = *(const float4*)(g_attvec + lane * 4);
    float4 c[3];
#pragma unroll
    for (int k = 0; k < 3; k++) {
        float4 g = ldh4(gate16 + (size_t)k * UF + base);
        float4 a = ldh4(n1 + (size_t)k * UF + base);
        float4 n = ldh4(n2 + (size_t)k * UF + base);
        c[k].x = g.x + a.x + n.x;
        c[k].y = g.y + a.y + n.y;
        c[k].z = g.z + a.z + n.z;
        c[k].w = g.w + a.w + n.w;
    }
    float w0 = c[0].x * v.x + c[0].y * v.y + c[0].z * v.z + c[0].w * v.w;
    float w1 = c[1].x * v.x + c[1].y * v.y + c[1].z * v.z + c[1].w * v.w;
    float w2 = c[2].x * v.x + c[2].y * v.y + c[2].z * v.z + c[2].w * v.w;
#pragma unroll
    for (int o = 16; o; o >>= 1) {
        w0 += __shfl_xor_sync(0xffffffffu, w0, o);
        w1 += __shfl_xor_sync(0xffffffffu, w1, o);
        w2 += __shfl_xor_sync(0xffffffffu, w2, o);
    }
    float m = fmaxf(w0, fmaxf(w1, w2));
    float e0 = expf(w0 - m), e1 = expf(w1 - m), e2 = expf(w2 - m);
    float inv = 1.f / (e0 + e1 + e2);
    e0 *= inv; e1 *= inv; e2 *= inv;
    float4 g3 = ldh4(gate16 + 3 * UF + base);
    float4 sa = ldh4(s1n + base);
    float4 sn = ldh4(s2n + base);
    float4 o;
    o.x = e0 * c[0].x + e1 * c[1].x + e2 * c[2].x + 0.5f * (g3.x + sa.x + sn.x);
    o.y = e0 * c[0].y + e1 * c[1].y + e2 * c[2].y + 0.5f * (g3.y + sa.y + sn.y);
    o.z = e0 * c[0].z + e1 * c[1].z + e2 * c[2].z + 0.5f * (g3.z + sa.z + sn.z);
    o.w = e0 * c[0].w + e1 * c[1].w + e2 * c[2].w + 0.5f * (g3.w + sa.w + sn.w);
    *(float4*)(out + base) = o;
}

// ------------------- item output: out = i_emb + i1n + i2n -------------------
__global__ void __launch_bounds__(256) item_out_kernel(const float* __restrict__ ie,
                                                       const __half* __restrict__ i1n,
                                                       const __half* __restrict__ i2n,
                                                       float* __restrict__ out) {
    int i = blockIdx.x * blockDim.x + threadIdx.x;
    if (i < (int)(IFl / 4)) {
        float4 a = __ldg((const float4*)ie + i);
        float4 b = ldh4(i1n + (size_t)i * 4);
        float4 n = ldh4(i2n + (size_t)i * 4);
        a.x += b.x + n.x; a.y += b.y + n.y; a.z += b.z + n.z; a.w += b.w + n.w;
        *((float4*)out + i) = a;
    }
}

// ------------------- host orchestration -------------------
extern "C" void kernel_launch(void* const* d_in, const int* in_sizes, int n_in,
                              void* d_out, int out_size) {
    const float* u_emb = (const float*)d_in[0];
    const float* i_emb = (const float*)d_in[1];
    const float* gW = (const float*)d_in[2];
    const float* gB = (const float*)d_in[3];
    const float* att = (const float*)d_in[4];
    const float* attm = (const float*)d_in[5];
    const int* Hr[3] = {(const int*)d_in[6], (const int*)d_in[9], (const int*)d_in[12]};
    const int* Hc[3] = {(const int*)d_in[7], (const int*)d_in[10], (const int*)d_in[13]};
    const float* Hv[3] = {(const float*)d_in[8], (const float*)d_in[11], (const float*)d_in[14]};
    const int* Rr = (const int*)d_in[15];
    const int* Rc = (const int*)d_in[16];
    const float* Rv = (const float*)d_in[17];
    int EH = in_sizes[6], ER = in_sizes[15];
    float* out = (float*)d_out;

    static __half* H = nullptr;
    static int *cnt = nullptr, *cur = nullptr, *offs = nullptr, *aux = nullptr;
    static int2* pair = nullptr;
    static cudaStream_t s2 = nullptr;
    static cudaEvent_t evFork = nullptr, evJoin = nullptr;
    if (!H) {
        cudaGetSymbolAddress((void**)&H, g_hbuf);
        cudaGetSymbolAddress((void**)&cnt, g_cnt);
        cudaGetSymbolAddress((void**)&cur, g_cur);
        cudaGetSymbolAddress((void**)&offs, g_offs);
        cudaGetSymbolAddress((void**)&pair, g_pair);
        cudaGetSymbolAddress((void**)&aux, g_aux);
        cudaFuncSetAttribute(gate_mma_kernel, cudaFuncAttributeMaxDynamicSharedMemorySize, GATE_SMEM);
        cudaStreamCreateWithFlags(&s2, cudaStreamNonBlocking);
        cudaEventCreateWithFlags(&evFork, cudaEventDisableTiming);
        cudaEventCreateWithFlags(&evJoin, cudaEventDisableTiming);
    }
    __half* gate16 = H + H_GATE;
    __half* curA16 = H + H_CURA;
    __half* mix16 = H + H_MIX;
    __half* s1_16 = H + H_S1;
    __half* n1_16 = H + H_N1;
    __half* n2_16 = H + H_N2;
    __half* s1n16 = H + H_S1N;
    __half* s2n16 = H + H_S2N;
    __half* i1_16 = H + H_I1;
    __half* i1n16 = H + H_I1N;
    __half* i2n16 = H + H_I2N;
    __half* iemb16 = H + H_IEMB;

#define GP16(c) (gate16 + (size_t)(c) * UF)
#define CA16(c) (curA16 + (size_t)(c) * UF)
#define N1(c) (n1_16 + (size_t)(c) * UF)
#define N2(c) (n2_16 + (size_t)(c) * UF)

    Build5 bj;
    for (int k = 0; k < 3; k++)
        bj.j[k] = {Hr[k], Hc[k], Hv[k], cnt + k * NU, cur + k * NU, offs + k * OSTR,
                   pair + (size_t)k * EHMAX, EH, NU};
    bj.j[3] = {Rr, Rc, Rv, cnt + 3 * NU, cur + 3 * NU, offs + 3 * OSTR,
               pair + 3 * (size_t)EHMAX, ER, NU};
    bj.j[4] = {Rc, Rr, Rv, cnt + 4 * NU, cur + 4 * NU, offs + 4 * OSTR,
               pair + 3 * (size_t)EHMAX + ERMAX, ER, NI};
    {
        int be[5];
        for (int k = 0; k < 5; k++) be[k] = (bj.j[k].ne + 255) / 256;
        bj.bstart[0] = 0;
        for (int k = 0; k < 5; k++) bj.bstart[k + 1] = bj.bstart[k] + be[k];
    }

    const int* offsR = bj.j[3].offs;  const int2* pairR = bj.j[3].pair;
    const int* offsRT = bj.j[4].offs; const int2* pairRT = bj.j[4].pair;

    // ---- fork: CSR build on s2, dense prologue on main ----
    cudaEventRecord(evFork, 0);
    cudaStreamWaitEvent(s2, evFork, 0);

    cudaMemsetAsync(cnt, 0, CNT_TOT * sizeof(int), s2);
    count_kernel<<<bj.bstart[5], 256, 0, s2>>>(bj);
    scan_chunks_kernel<<<dim3(NCHU, 5), 256, 0, s2>>>(bj, aux);
    scan_aux_kernel<<<1, 160, 0, s2>>>(bj, aux);
    scan_apply_kernel<<<dim3(NCHU, 5), 256, 0, s2>>>(bj, aux);
    scatter_kernel<<<bj.bstart[5], 256, 0, s2>>>(bj);
    cudaEventRecord(evJoin, s2);

    attvec_kernel<<<1, 128>>>(att, attm);
    f2h_kernel<<<(int)((IFl / 4 + 255) / 256), 256>>>(i_emb, iemb16, (int)(IFl / 4));
    gate_mma_kernel<<<dim3(148, 4), 256, GATE_SMEM>>>(u_emb, gW, gB, gate16);

    int mixb = (NU + 7) / 8;
    const int BU = (NU + 15) / 16;
    const int BI = (NI + 15) / 16;

    mix_h_kernel<<<mixb, 256>>>(GP16(0), GP16(1), GP16(2), GP16(3), mix16, NU);

    cudaStreamWaitEvent(0, evJoin, 0);   // join before SpMM

    // ---------------- layer 1: raw fp16 out + fp16 l2norm write ----------------
    {
        Csr5 a;
        for (int k = 0; k < 3; k++)
            a.j[k] = {bj.j[k].offs, bj.j[k].pair, GP16(k), CA16(k), N1(k), NU};
        a.j[3] = {offsRT, pairRT, mix16, i1_16, i1n16, NI};  // item1 = R^T @ mixed
        a.j[4] = {offsR, pairR, iemb16, s1_16, s1n16, NU};   // s1 = R @ i_emb
        a.bstart[0] = 0; a.bstart[1] = BU; a.bstart[2] = 2 * BU; a.bstart[3] = 3 * BU;
        a.bstart[4] = 3 * BU + BI; a.bstart[5] = 4 * BU + BI;
        spmm_csr5_kernel<<<a.bstart[5], 256>>>(a);
    }

    // ---------------- layer 2: fp16 l2norm only ----------------
    mix_h_kernel<<<mixb, 256>>>(CA16(0), CA16(1), CA16(2), s1_16, mix16, NU);
    {
        Csr5 a;
        for (int k = 0; k < 3; k++)
            a.j[k] = {bj.j[k].offs, bj.j[k].pair, CA16(k), nullptr, N2(k), NU};
        a.j[3] = {offsRT, pairRT, mix16, nullptr, i2n16, NI};  // l2n(R^T @ mixed2)
        a.j[4] = {offsR, pairR, i1_16, nullptr, s2n16, NU};    // l2n(R @ item1)
        a.bstart[0] = 0; a.bstart[1] = BU; a.bstart[2] = 2 * BU; a.bstart[3] = 3 * BU;
        a.bstart[4] = 3 * BU + BI; a.bstart[5] = 4 * BU + BI;
        spmm_csr5_kernel<<<a.bstart[5], 256>>>(a);
    }

    // ---------------- final ----------------
    mix_final_kernel<<<mixb, 256>>>(gate16, n1_16, n2_16, s1n16, s2n16, out, NU);
    item_out_kernel<<<(int)((IFl / 4 + 255) / 256), 256>>>(i_emb, i1n16, i2n16,
                                                           out + (size_t)NU * DIMV);
}